// round 2
// baseline (speedup 1.0000x reference)
#include <cuda_runtime.h>
#include <cstdint>

#define BB 64
#define SS 2048
#define II 64
#define HH 128
#define MROWS (BB*SS)

typedef unsigned long long ull;

// Scratch (no runtime allocation allowed): wx buffer (reused for both layers)
// and layer-0 output sequence. Referenced by symbol inside kernels so the
// host-side kernel_launch makes NO runtime API calls besides kernel launches.
__device__ __align__(256) float g_wx[(size_t)MROWS * HH];
__device__ __align__(256) float g_seq0[(size_t)MROWS * HH];

// ---------------- packed f32x2 helpers (sm_100+) ----------------
__device__ __forceinline__ ull packf2(float lo, float hi) {
    ull r; asm("mov.b64 %0, {%1, %2};" : "=l"(r) : "f"(lo), "f"(hi)); return r;
}
__device__ __forceinline__ float2 unpackf2(ull v) {
    float2 r; asm("mov.b64 {%0, %1}, %2;" : "=f"(r.x), "=f"(r.y) : "l"(v)); return r;
}
__device__ __forceinline__ ull ffma2(ull a, ull b, ull c) {
    ull d; asm("fma.rn.f32x2 %0, %1, %2, %3;" : "=l"(d) : "l"(a), "l"(b), "l"(c)); return d;
}
__device__ __forceinline__ void lds_v2u64(ull &p0, ull &p1, uint32_t addr) {
    asm volatile("ld.shared.v2.u64 {%0, %1}, [%2];" : "=l"(p0), "=l"(p1) : "r"(addr));
}
__device__ __forceinline__ float ex2f(float x) {
    float r; asm("ex2.approx.ftz.f32 %0, %1;" : "=f"(r) : "f"(x)); return r;
}
__device__ __forceinline__ float rcpf(float x) {
    float r; asm("rcp.approx.ftz.f32 %0, %1;" : "=f"(r) : "f"(x)); return r;
}
__device__ __forceinline__ float sigmoidf_(float x) {
    return rcpf(1.0f + ex2f(-1.4426950408889634f * x));
}
__device__ __forceinline__ float tanhf_(float x) {
    float e = ex2f(2.8853900817779268f * x);   // exp(2x)
    return 1.0f - 2.0f * rcpf(e + 1.0f);
}

// ---------------- GEMM: g_wx[M,128] = A[M,K] @ W[K,128] ----------------
// SRC = 0: A comes from the kernel parameter (x input).
// SRC = 1: A is g_seq0 (layer-0 output).
// Thread j keeps W column j in registers (packed f32x2); A rows staged
// through a shared tile and broadcast via ld.shared.v2.u64.
template<int K, int TILE, int SRC>
__global__ void __launch_bounds__(128) gemm_colreg(
    const float* __restrict__ Ain, const float* __restrict__ W)
{
    const float* __restrict__ A = (SRC == 0) ? Ain : (const float*)g_seq0;
    float* __restrict__ C = g_wx;

    const int j = threadIdx.x;
    ull wreg[K / 2];
#pragma unroll
    for (int m = 0; m < K / 2; m++)
        wreg[m] = packf2(W[(2 * m) * HH + j], W[(2 * m + 1) * HH + j]);

    __shared__ __align__(16) float As[TILE * K];
    const uint32_t as = (uint32_t)__cvta_generic_to_shared(As);

    const int rows_per_block = MROWS / gridDim.x;
    const int r0 = blockIdx.x * rows_per_block;

    for (int rt = 0; rt < rows_per_block; rt += TILE) {
        const float4* src = reinterpret_cast<const float4*>(A + (size_t)(r0 + rt) * K);
        float4* dst = reinterpret_cast<float4*>(As);
#pragma unroll
        for (int i = 0; i < (TILE * K / 4) / 128; i++)
            dst[i * 128 + j] = src[i * 128 + j];
        __syncthreads();

#pragma unroll
        for (int r = 0; r < TILE; r++) {
            ull a0 = packf2(0.f, 0.f), a1 = a0, a2 = a0, a3 = a0;
#pragma unroll
            for (int i = 0; i < K / 4; i++) {
                ull p0, p1;
                lds_v2u64(p0, p1, as + (uint32_t)(r * K * 4 + i * 16));
                if ((i & 1) == 0) {
                    a0 = ffma2(p0, wreg[2 * i], a0);
                    a1 = ffma2(p1, wreg[2 * i + 1], a1);
                } else {
                    a2 = ffma2(p0, wreg[2 * i], a2);
                    a3 = ffma2(p1, wreg[2 * i + 1], a3);
                }
            }
            float2 f0 = unpackf2(a0), f1 = unpackf2(a1);
            float2 f2 = unpackf2(a2), f3 = unpackf2(a3);
            float s = ((f0.x + f0.y) + (f1.x + f1.y)) + ((f2.x + f2.y) + (f3.x + f3.y));
            C[(size_t)(r0 + rt + r) * HH + j] = s;
        }
        __syncthreads();
    }
}

// ---------------- Recurrent scan: one CTA per batch ----------------
// Reads wx from g_wx. OUT_SEL = 0: write sequence to g_seq0 (layer 0).
// OUT_SEL = 1: write sequence to the out parameter (layer 1 -> d_out).
// h double-buffered in SMEM (one barrier/step); u column j in registers;
// wx[t] prefetched CH steps ahead in a register ring to hide DRAM latency.
template<int OUT_SEL>
__global__ void __launch_bounds__(128) scan_kernel(
    const float* __restrict__ u,     // [H,H]
    const float* __restrict__ bg, const float* __restrict__ bu,
    const float* __restrict__ zeta, const float* __restrict__ nu,
    const float* __restrict__ lambd, const float* __restrict__ gamma,
    float* __restrict__ out_param,   // [B,S,H] (used when OUT_SEL==1)
    float* __restrict__ h_last)      // [B,H]
{
    const float* __restrict__ wx = g_wx;
    float* __restrict__ out_seq = (OUT_SEL == 0) ? (float*)g_seq0 : out_param;

    const int b = blockIdx.x;
    const int j = threadIdx.x;

    __shared__ __align__(16) float hs[2][HH];

    ull ureg[HH / 2];
#pragma unroll
    for (int m = 0; m < HH / 2; m++)
        ureg[m] = packf2(u[(2 * m) * HH + j], u[(2 * m + 1) * HH + j]);

    const float bgj = bg[j], buj = bu[j];
    const float sz = sigmoidf_(zeta[0]);
    const float sn = sigmoidf_(nu[0]);
    float gc = gamma[0];
    gc = fminf(fmaxf(gc, 0.0f), 1.0f);
    const float c1 = (1.0f - gc) * lambd[0];

    const uint32_t hb = (uint32_t)__cvta_generic_to_shared(&hs[0][0]);
    const float* wb = wx + (size_t)b * SS * HH + j;
    float* ob = out_seq + (size_t)b * SS * HH + j;

    float hprev = 0.0f;
    hs[0][j] = 0.0f;
    __syncthreads();

    constexpr int CH = 4;                 // prefetch distance (steps)
    float wcur[CH];
#pragma unroll
    for (int d = 0; d < CH; d++) wcur[d] = wb[(size_t)d * HH];

    for (int tc = 0; tc < SS; tc += CH) {
        float wnew[CH];
#pragma unroll
        for (int d = 0; d < CH; d++) {
            int tn = tc + CH + d;
            wnew[d] = (tn < SS) ? wb[(size_t)tn * HH] : 0.0f;
        }
#pragma unroll
        for (int d = 0; d < CH; d++) {
            const int t = tc + d;
            const uint32_t ra = hb + ((t & 1) ? 512u : 0u);   // read buffer
            ull a0 = packf2(0.f, 0.f), a1 = a0, a2 = a0, a3 = a0;
#pragma unroll
            for (int i = 0; i < HH / 4; i++) {
                ull p0, p1;
                lds_v2u64(p0, p1, ra + (uint32_t)(i * 16));
                if ((i & 1) == 0) {
                    a0 = ffma2(p0, ureg[2 * i], a0);
                    a1 = ffma2(p1, ureg[2 * i + 1], a1);
                } else {
                    a2 = ffma2(p0, ureg[2 * i], a2);
                    a3 = ffma2(p1, ureg[2 * i + 1], a3);
                }
            }
            float2 f0 = unpackf2(a0), f1 = unpackf2(a1);
            float2 f2 = unpackf2(a2), f3 = unpackf2(a3);
            float pre = wcur[d] +
                (((f0.x + f0.y) + (f1.x + f1.y)) + ((f2.x + f2.y) + (f3.x + f3.y)));

            float z  = sigmoidf_(pre + bgj);
            float hh = tanhf_(pre + buj);
            float hn = z * hprev + (sz * (1.0f - z) + sn) * hh;
            float hc = gc * hn + c1;

            hs[(t & 1) ^ 1][j] = hc;       // write other buffer
            ob[(size_t)t * HH] = hc;       // stream output (fire & forget)
            hprev = hc;
            __syncthreads();               // one barrier per step
        }
#pragma unroll
        for (int d = 0; d < CH; d++) wcur[d] = wnew[d];
    }
    h_last[b * HH + j] = hprev;
}

// ---------------- launch ----------------
extern "C" void kernel_launch(void* const* d_in, const int* in_sizes, int n_in,
                              void* d_out, int out_size)
{
    const float* x      = (const float*)d_in[0];
    const float* w0     = (const float*)d_in[1];
    const float* u0     = (const float*)d_in[2];
    const float* bg0    = (const float*)d_in[3];
    const float* bu0    = (const float*)d_in[4];
    const float* zeta0  = (const float*)d_in[5];
    const float* nu0    = (const float*)d_in[6];
    const float* lambd0 = (const float*)d_in[7];
    const float* gamma0 = (const float*)d_in[8];
    const float* w1     = (const float*)d_in[9];
    const float* u1     = (const float*)d_in[10];
    const float* bg1    = (const float*)d_in[11];
    const float* bu1    = (const float*)d_in[12];
    const float* zeta1  = (const float*)d_in[13];
    const float* nu1    = (const float*)d_in[14];
    const float* lambd1 = (const float*)d_in[15];
    const float* gamma1 = (const float*)d_in[16];

    float* out1 = (float*)d_out;                          // [B,S,H]
    float* hn   = out1 + (size_t)BB * SS * HH;            // [2,B,H]

    // Phase 1: g_wx = x @ w0   (K=64)
    gemm_colreg<II, 16, 0><<<1024, 128>>>(x, w0);
    // Phase 2: layer-0 scan (g_wx -> g_seq0), h0_T
    scan_kernel<0><<<BB, 128>>>(u0, bg0, bu0, zeta0, nu0, lambd0, gamma0,
                                nullptr, hn);
    // Phase 3: g_wx = g_seq0 @ w1 (K=128)
    gemm_colreg<HH, 16, 1><<<1024, 128>>>(nullptr, w1);
    // Phase 4: layer-1 scan (g_wx -> d_out), h1_T
    scan_kernel<1><<<BB, 128>>>(u1, bg1, bu1, zeta1, nu1, lambd1, gamma1,
                                out1, hn + BB * HH);
}

// round 3
// speedup vs baseline: 1.2493x; 1.2493x over previous
#include <cuda_runtime.h>
#include <cstdint>

#define BB 64
#define SS 2048
#define II 64
#define HH 128
#define MROWS (BB*SS)

typedef unsigned long long ull;

// Scratch (no runtime allocation allowed).
__device__ __align__(256) float g_wx[(size_t)MROWS * HH];
__device__ __align__(256) float g_seq0[(size_t)MROWS * HH];

// ---------------- packed f32x2 helpers (sm_100+) ----------------
__device__ __forceinline__ ull packf2(float lo, float hi) {
    ull r; asm("mov.b64 %0, {%1, %2};" : "=l"(r) : "f"(lo), "f"(hi)); return r;
}
__device__ __forceinline__ float2 unpackf2(ull v) {
    float2 r; asm("mov.b64 {%0, %1}, %2;" : "=f"(r.x), "=f"(r.y) : "l"(v)); return r;
}
__device__ __forceinline__ ull ffma2(ull a, ull b, ull c) {
    ull d; asm("fma.rn.f32x2 %0, %1, %2, %3;" : "=l"(d) : "l"(a), "l"(b), "l"(c)); return d;
}
__device__ __forceinline__ void lds_v2u64(ull &p0, ull &p1, uint32_t addr) {
    asm volatile("ld.shared.v2.u64 {%0, %1}, [%2];" : "=l"(p0), "=l"(p1) : "r"(addr));
}
__device__ __forceinline__ float ex2f(float x) {
    float r; asm("ex2.approx.ftz.f32 %0, %1;" : "=f"(r) : "f"(x)); return r;
}
__device__ __forceinline__ float rcpf(float x) {
    float r; asm("rcp.approx.ftz.f32 %0, %1;" : "=f"(r) : "f"(x)); return r;
}
__device__ __forceinline__ float sigmoidf_(float x) {
    return rcpf(1.0f + ex2f(-1.4426950408889634f * x));
}
__device__ __forceinline__ float tanhf_(float x) {
    float e = ex2f(2.8853900817779268f * x);   // exp(2x)
    return 1.0f - 2.0f * rcpf(e + 1.0f);
}

// ---------------- GEMM: g_wx[M,128] = A[M,K] @ W[K,128] ----------------
template<int K, int TILE, int SRC>
__global__ void __launch_bounds__(128) gemm_colreg(
    const float* __restrict__ Ain, const float* __restrict__ W)
{
    const float* __restrict__ A = (SRC == 0) ? Ain : (const float*)g_seq0;
    float* __restrict__ C = g_wx;

    const int j = threadIdx.x;
    ull wreg[K / 2];
#pragma unroll
    for (int m = 0; m < K / 2; m++)
        wreg[m] = packf2(W[(2 * m) * HH + j], W[(2 * m + 1) * HH + j]);

    __shared__ __align__(16) float As[TILE * K];
    const uint32_t as = (uint32_t)__cvta_generic_to_shared(As);

    const int rows_per_block = MROWS / gridDim.x;
    const int r0 = blockIdx.x * rows_per_block;

    for (int rt = 0; rt < rows_per_block; rt += TILE) {
        const float4* src = reinterpret_cast<const float4*>(A + (size_t)(r0 + rt) * K);
        float4* dst = reinterpret_cast<float4*>(As);
#pragma unroll
        for (int i = 0; i < (TILE * K / 4) / 128; i++)
            dst[i * 128 + j] = src[i * 128 + j];
        __syncthreads();

#pragma unroll
        for (int r = 0; r < TILE; r++) {
            ull a0 = packf2(0.f, 0.f), a1 = a0, a2 = a0, a3 = a0;
#pragma unroll
            for (int i = 0; i < K / 4; i++) {
                ull p0, p1;
                lds_v2u64(p0, p1, as + (uint32_t)(r * K * 4 + i * 16));
                if ((i & 1) == 0) {
                    a0 = ffma2(p0, wreg[2 * i], a0);
                    a1 = ffma2(p1, wreg[2 * i + 1], a1);
                } else {
                    a2 = ffma2(p0, wreg[2 * i], a2);
                    a3 = ffma2(p1, wreg[2 * i + 1], a3);
                }
            }
            float2 f0 = unpackf2(a0), f1 = unpackf2(a1);
            float2 f2 = unpackf2(a2), f3 = unpackf2(a3);
            float s = ((f0.x + f0.y) + (f1.x + f1.y)) + ((f2.x + f2.y) + (f3.x + f3.y));
            C[(size_t)(r0 + rt + r) * HH + j] = s;
        }
        __syncthreads();
    }
}

// ---------------- Recurrent scan: 512 threads, 4-way k-split ----------------
// Thread (q, c): q = lane>>3 (k-quarter), c = warp*8 + (lane&7) (column).
// Each thread holds u[32q:32q+32, c] in 16 packed regs, computes a 32-long
// partial dot from padded shared h, reduces the 4 partials with 2 shfl.bfly
// (same warp), computes gates redundantly; q==0 lanes commit h and output.
// One __syncthreads per step (double-buffered h).
#define QPAD 36   // floats per 32-value quarter (144B) -> conflict-free quads
template<int OUT_SEL>
__global__ void __launch_bounds__(512) scan_kernel(
    const float* __restrict__ u,     // [H,H]
    const float* __restrict__ bg, const float* __restrict__ bu,
    const float* __restrict__ zeta, const float* __restrict__ nu,
    const float* __restrict__ lambd, const float* __restrict__ gamma,
    float* __restrict__ out_param,   // [B,S,H] (used when OUT_SEL==1)
    float* __restrict__ h_last)      // [B,H]
{
    const float* __restrict__ wx = g_wx;
    float* __restrict__ out_seq = (OUT_SEL == 0) ? (float*)g_seq0 : out_param;

    const int b    = blockIdx.x;
    const int tid  = threadIdx.x;
    const int w    = tid >> 5;
    const int lane = tid & 31;
    const int q    = lane >> 3;            // k-quarter 0..3
    const int c    = (w << 3) + (lane & 7);// column 0..127

    __shared__ __align__(16) float hs[2][4 * QPAD];

    // u slice: k in [32q, 32q+32), column c -> 16 packed f32x2
    ull ureg[16];
#pragma unroll
    for (int m = 0; m < 16; m++) {
        int k0 = 32 * q + 2 * m;
        ureg[m] = packf2(u[(size_t)k0 * HH + c], u[(size_t)(k0 + 1) * HH + c]);
    }

    const float bgj = bg[c], buj = bu[c];
    const float sz = sigmoidf_(zeta[0]);
    const float sn = sigmoidf_(nu[0]);
    float gc = gamma[0];
    gc = fminf(fmaxf(gc, 0.0f), 1.0f);
    const float c1 = (1.0f - gc) * lambd[0];

    const uint32_t hb = (uint32_t)__cvta_generic_to_shared(&hs[0][0]);
    const uint32_t qoff = (uint32_t)(q * QPAD * 4);
    const float* wb = wx + (size_t)b * SS * HH + c;
    float* ob = out_seq + (size_t)b * SS * HH + c;

    // init h = 0 in buffer 0 (padded layout)
    if (tid < HH) hs[0][(tid >> 5) * QPAD + (tid & 31)] = 0.0f;
    float hprev = 0.0f;
    __syncthreads();

    constexpr int CH = 8;                 // wx prefetch distance (steps)
    float wcur[CH];
#pragma unroll
    for (int d = 0; d < CH; d++) wcur[d] = wb[(size_t)d * HH];

    for (int tc = 0; tc < SS; tc += CH) {
        float wnew[CH];
#pragma unroll
        for (int d = 0; d < CH; d++) {
            int tn = tc + CH + d;
            wnew[d] = (tn < SS) ? wb[(size_t)tn * HH] : 0.0f;
        }
#pragma unroll
        for (int d = 0; d < CH; d++) {
            const int t = tc + d;
            const uint32_t ra = hb + ((t & 1) ? (uint32_t)(4 * QPAD * 4) : 0u) + qoff;

            ull a0 = packf2(0.f, 0.f), a1 = a0;
#pragma unroll
            for (int i = 0; i < 8; i++) {
                ull p0, p1;
                lds_v2u64(p0, p1, ra + (uint32_t)(i * 16));
                a0 = ffma2(p0, ureg[2 * i], a0);
                a1 = ffma2(p1, ureg[2 * i + 1], a1);
            }
            float2 f0 = unpackf2(a0), f1 = unpackf2(a1);
            float p = (f0.x + f0.y) + (f1.x + f1.y);
            // reduce the 4 k-quarters (lanes differing in bits 3,4)
            p += __shfl_xor_sync(0xffffffffu, p, 8);
            p += __shfl_xor_sync(0xffffffffu, p, 16);

            float pre = p + wcur[d];
            float z  = sigmoidf_(pre + bgj);
            float hh = tanhf_(pre + buj);
            float hn = z * hprev + (sz * (1.0f - z) + sn) * hh;
            float hc = gc * hn + c1;

            if (q == 0) {
                hs[(t & 1) ^ 1][(c >> 5) * QPAD + (c & 31)] = hc;
                ob[(size_t)t * HH] = hc;
            }
            hprev = hc;
            __syncthreads();               // one barrier per step
        }
#pragma unroll
        for (int d = 0; d < CH; d++) wcur[d] = wnew[d];
    }
    if (q == 0) h_last[b * HH + c] = hprev;
}

// ---------------- launch ----------------
extern "C" void kernel_launch(void* const* d_in, const int* in_sizes, int n_in,
                              void* d_out, int out_size)
{
    const float* x      = (const float*)d_in[0];
    const float* w0     = (const float*)d_in[1];
    const float* u0     = (const float*)d_in[2];
    const float* bg0    = (const float*)d_in[3];
    const float* bu0    = (const float*)d_in[4];
    const float* zeta0  = (const float*)d_in[5];
    const float* nu0    = (const float*)d_in[6];
    const float* lambd0 = (const float*)d_in[7];
    const float* gamma0 = (const float*)d_in[8];
    const float* w1     = (const float*)d_in[9];
    const float* u1     = (const float*)d_in[10];
    const float* bg1    = (const float*)d_in[11];
    const float* bu1    = (const float*)d_in[12];
    const float* zeta1  = (const float*)d_in[13];
    const float* nu1    = (const float*)d_in[14];
    const float* lambd1 = (const float*)d_in[15];
    const float* gamma1 = (const float*)d_in[16];

    float* out1 = (float*)d_out;                          // [B,S,H]
    float* hn   = out1 + (size_t)BB * SS * HH;            // [2,B,H]

    // Phase 1: g_wx = x @ w0   (K=64)
    gemm_colreg<II, 16, 0><<<1024, 128>>>(x, w0);
    // Phase 2: layer-0 scan (g_wx -> g_seq0), h0_T
    scan_kernel<0><<<BB, 512>>>(u0, bg0, bu0, zeta0, nu0, lambd0, gamma0,
                                nullptr, hn);
    // Phase 3: g_wx = g_seq0 @ w1 (K=128)
    gemm_colreg<HH, 16, 1><<<1024, 128>>>(nullptr, w1);
    // Phase 4: layer-1 scan (g_wx -> d_out), h1_T
    scan_kernel<1><<<BB, 512>>>(u1, bg1, bu1, zeta1, nu1, lambd1, gamma1,
                                out1, hn + BB * HH);
}

// round 5
// speedup vs baseline: 2.2676x; 1.8151x over previous
#include <cuda_runtime.h>
#include <cstdint>

#define BB 64
#define SS 2048
#define II 64
#define HH 128
#define CH 8
#define MROWS (BB*SS)

typedef unsigned long long ull;

// Scratch + inter-CTA progress flags (no runtime allocation allowed).
__device__ __align__(256) float g_seq0[(size_t)MROWS * HH];
__device__ unsigned g_flag[BB];

// ---------------- packed f32x2 helpers (sm_100+) ----------------
__device__ __forceinline__ ull packf2(float lo, float hi) {
    ull r; asm("mov.b64 %0, {%1, %2};" : "=l"(r) : "f"(lo), "f"(hi)); return r;
}
__device__ __forceinline__ float2 unpackf2(ull v) {
    float2 r; asm("mov.b64 {%0, %1}, %2;" : "=f"(r.x), "=f"(r.y) : "l"(v)); return r;
}
__device__ __forceinline__ ull ffma2(ull a, ull b, ull c) {
    ull d; asm("fma.rn.f32x2 %0, %1, %2, %3;" : "=l"(d) : "l"(a), "l"(b), "l"(c)); return d;
}
__device__ __forceinline__ void lds_v2u64(ull &p0, ull &p1, uint32_t addr) {
    asm volatile("ld.shared.v2.u64 {%0, %1}, [%2];" : "=l"(p0), "=l"(p1) : "r"(addr));
}
__device__ __forceinline__ float ex2f(float x) {
    float r; asm("ex2.approx.ftz.f32 %0, %1;" : "=f"(r) : "f"(x)); return r;
}
__device__ __forceinline__ float rcpf(float x) {
    float r; asm("rcp.approx.ftz.f32 %0, %1;" : "=f"(r) : "f"(x)); return r;
}
__device__ __forceinline__ float sigmoidf_(float x) {
    return rcpf(1.0f + ex2f(-1.4426950408889634f * x));
}
__device__ __forceinline__ float tanhf_(float x) {
    float e = ex2f(2.8853900817779268f * x);   // exp(2x)
    return 1.0f - 2.0f * rcpf(e + 1.0f);
}
__device__ __forceinline__ unsigned ld_acquire(const unsigned* p) {
    unsigned v;
    asm volatile("ld.acquire.gpu.global.u32 %0, [%1];" : "=r"(v) : "l"(p) : "memory");
    return v;
}
__device__ __forceinline__ void st_release(unsigned* p, unsigned v) {
    asm volatile("st.release.gpu.global.u32 [%0], %1;" :: "l"(p), "r"(v) : "memory");
}

__global__ void zero_flags() {
    if (threadIdx.x < BB) g_flag[threadIdx.x] = 0;
}

// ---------------- fused scan role ----------------
// One CTA = one (layer, batch). 256 threads, 8 warps. Thread (q,c):
//   q = lane>>4 (k-half), c = warp*16 + (lane&15) (output column).
// Registers: u[64q:64q+64, c] (32 ull) for the recurrent dot,
//            W[KH*q : KH*q+KH, c] for the fused input projection.
// Per chunk of CH=8 steps: stage CH input rows in padded smem, precompute
// the CH input-projection partials OFF the serial path, then run 8 serial
// steps (h double-buffered in smem, one __syncthreads per step, partial
// sums reduced across the 2 k-halves with a single shfl.xor 16).
// PROD: writes out rows + release-flag per chunk. !PROD: acquire-waits on
// the producer's flag before (pre)loading its rows.
template<int KF, bool PROD>
__device__ __forceinline__ void scan_role(
    float* hs, float* xt,
    const float* __restrict__ xsrc,   // rows of width KF, stride KF
    const float* __restrict__ u,      // [H,H]
    const float* __restrict__ w,      // [KF,H]
    const float* bg, const float* bu,
    const float* zeta, const float* nu,
    const float* lambd, const float* gamma,
    float* __restrict__ outp,         // [S,H] slice for this batch
    float* __restrict__ hl,           // [H] slice for this batch
    unsigned* flagp)                  // wait on it (!PROD) or set it (PROD)
{
    constexpr int KH = KF / 2;        // 32 or 64
    constexpr int KP = KH + 4;        // padded half width (36 or 68)
    constexpr int CPR = KF / 4;       // float4s per row (16 or 32)
    constexpr int NV4 = CH * CPR;     // float4 staging loads (128 or 256)

    const int tid  = threadIdx.x;
    const int lane = tid & 31;
    const int wp   = tid >> 5;
    const int q    = lane >> 4;             // k-half
    const int c    = wp * 16 + (lane & 15); // column 0..127

    // Pinned register slices
    ull ureg[32];
#pragma unroll
    for (int m = 0; m < 32; m++) {
        int k0 = 64 * q + 2 * m;
        ureg[m] = packf2(u[(size_t)k0 * HH + c], u[(size_t)(k0 + 1) * HH + c]);
    }
    ull wreg[KH / 2];
#pragma unroll
    for (int m = 0; m < KH / 2; m++) {
        int k0 = KH * q + 2 * m;
        wreg[m] = packf2(w[(size_t)k0 * HH + c], w[(size_t)(k0 + 1) * HH + c]);
    }

    const float bgj = bg[c], buj = bu[c];
    const float sz = sigmoidf_(zeta[0]);
    const float sn = sigmoidf_(nu[0]);
    float gc = gamma[0];
    gc = fminf(fmaxf(gc, 0.0f), 1.0f);
    const float c1 = (1.0f - gc) * lambd[0];

    const uint32_t hb = (uint32_t)__cvta_generic_to_shared(hs);
    const uint32_t xb = (uint32_t)__cvta_generic_to_shared(xt);
    const uint32_t qoffH = (uint32_t)(q * 68 * 4);   // h half offset (bytes)
    const uint32_t qoffX = (uint32_t)(q * KP * 4);   // tile half offset

    // Staging thread map: thread -> (chunk row, float4 column).
    const int rowd = tid / CPR;            // 0..CH-1 (tid < NV4)
    const int e    = (tid % CPR) * 4;      // float column within row
    const int ehalf = e / KH, ewit = e % KH;

    // init h = 0 in buffer 0 (padded halves of 68)
    if (tid < HH) hs[(tid >> 6) * 68 + (tid & 63)] = 0.0f;
    float hprev = 0.0f;

    // ---- prologue: wait for first chunk (consumer) and load rows 0..CH-1
    if (!PROD) {
        while (ld_acquire(flagp) < CH) { }
    }
    float4 sreg = make_float4(0.f, 0.f, 0.f, 0.f);
    if (tid < NV4)
        sreg = __ldcg(reinterpret_cast<const float4*>(xsrc + (size_t)rowd * KF + e));

    for (int tc = 0; tc < SS; tc += CH) {
        // stage current chunk rows into the padded tile
        if (tid < NV4)
            *reinterpret_cast<float4*>(&xt[rowd * (2 * KP) + ehalf * KP + ewit]) = sreg;
        __syncthreads();

        // prefetch next chunk rows (after flag for consumer)
        if (tc + CH < SS) {
            if (!PROD) {
                while (ld_acquire(flagp) < (unsigned)(tc + 2 * CH)) { }
            }
            if (tid < NV4)
                sreg = __ldcg(reinterpret_cast<const float4*>(
                    xsrc + (size_t)(tc + CH + rowd) * KF + e));
        }

        // precompute input-projection partials for the chunk (off serial path)
        float xw[CH];
#pragma unroll
        for (int d = 0; d < CH; d++) {
            ull b0 = packf2(0.f, 0.f), b1 = b0;
            const uint32_t base = xb + (uint32_t)(d * (2 * KP) * 4) + qoffX;
#pragma unroll
            for (int i = 0; i < KH / 4; i++) {
                ull p0, p1;
                lds_v2u64(p0, p1, base + (uint32_t)(i * 16));
                b0 = ffma2(p0, wreg[2 * i], b0);
                b1 = ffma2(p1, wreg[2 * i + 1], b1);
            }
            float2 f0 = unpackf2(b0), f1 = unpackf2(b1);
            xw[d] = (f0.x + f0.y) + (f1.x + f1.y);
        }

        // serial steps
#pragma unroll
        for (int d = 0; d < CH; d++) {
            const int t = tc + d;
            const uint32_t ra = hb + ((t & 1) ? (uint32_t)(2 * 68 * 4) : 0u) + qoffH;
            ull a0 = packf2(0.f, 0.f), a1 = a0;
#pragma unroll
            for (int i = 0; i < 16; i++) {
                ull p0, p1;
                lds_v2u64(p0, p1, ra + (uint32_t)(i * 16));
                a0 = ffma2(p0, ureg[2 * i], a0);
                a1 = ffma2(p1, ureg[2 * i + 1], a1);
            }
            float2 f0 = unpackf2(a0), f1 = unpackf2(a1);
            float part = (f0.x + f0.y) + (f1.x + f1.y) + xw[d];
            float pre = part + __shfl_xor_sync(0xffffffffu, part, 16);

            float z  = sigmoidf_(pre + bgj);
            float hh = tanhf_(pre + buj);
            float hn = z * hprev + (sz * (1.0f - z) + sn) * hh;
            float hc = gc * hn + c1;

            if (lane < 16) {
                hs[((t & 1) ^ 1) * (2 * 68) + (c >> 6) * 68 + (c & 63)] = hc;
                outp[(size_t)t * HH + c] = hc;
            }
            hprev = hc;
            __syncthreads();
        }

        if (PROD) {
            __threadfence();
            __syncthreads();
            if (tid == 0) st_release(flagp, (unsigned)(tc + CH));
        }
    }
    if (lane < 16) hl[c] = hprev;
}

// ---------------- fused persistent kernel: 64 producer + 64 consumer CTAs
__global__ void __launch_bounds__(256) fused_grnn(
    const float* __restrict__ x,
    const float* __restrict__ u0, const float* __restrict__ w0,
    const float* __restrict__ bg0, const float* __restrict__ bu0,
    const float* __restrict__ zeta0, const float* __restrict__ nu0,
    const float* __restrict__ lambd0, const float* __restrict__ gamma0,
    const float* __restrict__ u1, const float* __restrict__ w1,
    const float* __restrict__ bg1, const float* __restrict__ bu1,
    const float* __restrict__ zeta1, const float* __restrict__ nu1,
    const float* __restrict__ lambd1, const float* __restrict__ gamma1,
    float* __restrict__ out1, float* __restrict__ hn)
{
    __shared__ __align__(16) float hs[2 * 2 * 68];
    __shared__ __align__(16) float xt[CH * 2 * 68];

    const int rank = blockIdx.x;
    if (rank < BB) {
        const int b = rank;
        scan_role<II, true>(hs, xt,
            x + (size_t)b * SS * II, u0, w0,
            bg0, bu0, zeta0, nu0, lambd0, gamma0,
            (float*)g_seq0 + (size_t)b * SS * HH,
            hn + (size_t)b * HH,
            &g_flag[b]);
    } else {
        const int b = rank - BB;
        scan_role<HH, false>(hs, xt,
            (const float*)g_seq0 + (size_t)b * SS * HH, u1, w1,
            bg1, bu1, zeta1, nu1, lambd1, gamma1,
            out1 + (size_t)b * SS * HH,
            hn + (size_t)(BB + b) * HH,
            &g_flag[b]);
    }
}

// ---------------- launch ----------------
extern "C" void kernel_launch(void* const* d_in, const int* in_sizes, int n_in,
                              void* d_out, int out_size)
{
    const float* x      = (const float*)d_in[0];
    const float* w0     = (const float*)d_in[1];
    const float* u0     = (const float*)d_in[2];
    const float* bg0    = (const float*)d_in[3];
    const float* bu0    = (const float*)d_in[4];
    const float* zeta0  = (const float*)d_in[5];
    const float* nu0    = (const float*)d_in[6];
    const float* lambd0 = (const float*)d_in[7];
    const float* gamma0 = (const float*)d_in[8];
    const float* w1     = (const float*)d_in[9];
    const float* u1     = (const float*)d_in[10];
    const float* bg1    = (const float*)d_in[11];
    const float* bu1    = (const float*)d_in[12];
    const float* zeta1  = (const float*)d_in[13];
    const float* nu1    = (const float*)d_in[14];
    const float* lambd1 = (const float*)d_in[15];
    const float* gamma1 = (const float*)d_in[16];

    float* out1 = (float*)d_out;                          // [B,S,H]
    float* hn   = out1 + (size_t)BB * SS * HH;            // [2,B,H]

    zero_flags<<<1, 64>>>();
    fused_grnn<<<2 * BB, 256>>>(x,
        u0, w0, bg0, bu0, zeta0, nu0, lambd0, gamma0,
        u1, w1, bg1, bu1, zeta1, nu1, lambd1, gamma1,
        out1, hn);
}

// round 6
// speedup vs baseline: 2.6249x; 1.1575x over previous
#include <cuda_runtime.h>
#include <cstdint>

#define BB 64
#define SS 2048
#define II 64
#define HH 128
#define CH 8
#define NCH (SS/CH)
#define MROWS (BB*SS)

typedef unsigned long long ull;

// Scratch + inter-CTA progress flags (no runtime allocation allowed).
__device__ __align__(256) float g_seq0[(size_t)MROWS * HH];
__device__ unsigned g_flag[BB];

#define BAR_SYNC(id, cnt)  asm volatile("bar.sync %0, %1;"   :: "r"(id), "r"(cnt) : "memory")
#define BAR_ARRIVE(id, cnt) asm volatile("bar.arrive %0, %1;" :: "r"(id), "r"(cnt) : "memory")

// ---------------- packed f32x2 helpers (sm_100+) ----------------
__device__ __forceinline__ ull packf2(float lo, float hi) {
    ull r; asm("mov.b64 %0, {%1, %2};" : "=l"(r) : "f"(lo), "f"(hi)); return r;
}
__device__ __forceinline__ float2 unpackf2(ull v) {
    float2 r; asm("mov.b64 {%0, %1}, %2;" : "=f"(r.x), "=f"(r.y) : "l"(v)); return r;
}
__device__ __forceinline__ ull ffma2(ull a, ull b, ull c) {
    ull d; asm("fma.rn.f32x2 %0, %1, %2, %3;" : "=l"(d) : "l"(a), "l"(b), "l"(c)); return d;
}
__device__ __forceinline__ void lds_v2u64(ull &p0, ull &p1, uint32_t addr) {
    asm volatile("ld.shared.v2.u64 {%0, %1}, [%2];" : "=l"(p0), "=l"(p1) : "r"(addr));
}
__device__ __forceinline__ float ex2f(float x) {
    float r; asm("ex2.approx.ftz.f32 %0, %1;" : "=f"(r) : "f"(x)); return r;
}
__device__ __forceinline__ float rcpf(float x) {
    float r; asm("rcp.approx.ftz.f32 %0, %1;" : "=f"(r) : "f"(x)); return r;
}
__device__ __forceinline__ float sigmoidf_(float x) {
    return rcpf(1.0f + ex2f(-1.4426950408889634f * x));
}
__device__ __forceinline__ float tanhf_(float x) {
    float e = ex2f(2.8853900817779268f * x);   // exp(2x)
    return 1.0f - 2.0f * rcpf(e + 1.0f);
}
__device__ __forceinline__ unsigned ld_acquire(const unsigned* p) {
    unsigned v;
    asm volatile("ld.acquire.gpu.global.u32 %0, [%1];" : "=r"(v) : "l"(p) : "memory");
    return v;
}
__device__ __forceinline__ void st_release(unsigned* p, unsigned v) {
    asm volatile("st.release.gpu.global.u32 [%0], %1;" :: "l"(p), "r"(v) : "memory");
}

__global__ void zero_flags() {
    if (threadIdx.x < BB) g_flag[threadIdx.x] = 0;
}

// ---------------- warp-specialized role ----------------
// CTA = one (layer, batch), 512 threads.
//  tid <  256: SCAN warps. Thread (q,c): q=lane>>4 (k-half), c=warp*16+(lane&15).
//              ureg = u[64q:64q+64, c]. Per step: 16 LDS.128 + 32 ffma2 (4 chains),
//              + xw from smem, shfl-reduce halves, gates, h double-buffer, bar 1.
//  tid >= 256: PROJ warps. Thread (qp,cp) 2-way k-split of W. Stage CH input rows
//              (double-buffered xt), compute xw chunk into double-buffered xw_s,
//              handshake with scan via named barriers 2..5. Consumer proj warps
//              absorb the producer-flag acquire spin.
template<int KF, bool PROD>
__device__ __forceinline__ void role(
    float* hs, float* xt, float* xw_s,
    const float* __restrict__ xsrc,   // rows of width KF
    const float* __restrict__ u,      // [H,H]
    const float* __restrict__ w,      // [KF,H]
    const float* bg, const float* bu,
    const float* zeta, const float* nu,
    const float* lambd, const float* gamma,
    float* __restrict__ outp,         // [S,H] slice
    float* __restrict__ hl,           // [H] slice
    unsigned* flagp)
{
    constexpr int KH = KF / 2;        // 32 or 64
    constexpr int KP = KH + 4;        // padded half width
    constexpr int CPR = KF / 4;       // float4s per row
    constexpr int NV4 = CH * CPR;     // staged float4s per chunk (<=256)
    constexpr int XTS = CH * 2 * 68;  // xt buffer stride (floats), max layout

    const int tid  = threadIdx.x;
    const int lane = tid & 31;

    if (tid < 256) {
        // ================= SCAN =================
        const int wp = tid >> 5;
        const int q  = lane >> 4;
        const int c  = wp * 16 + (lane & 15);

        ull ureg[32];
#pragma unroll
        for (int m = 0; m < 32; m++) {
            int k0 = 64 * q + 2 * m;
            ureg[m] = packf2(u[(size_t)k0 * HH + c], u[(size_t)(k0 + 1) * HH + c]);
        }
        const float bgj = bg[c], buj = bu[c];
        const float sz = sigmoidf_(zeta[0]);
        const float sn = sigmoidf_(nu[0]);
        float gc = gamma[0];
        gc = fminf(fmaxf(gc, 0.0f), 1.0f);
        const float c1 = (1.0f - gc) * lambd[0];

        const uint32_t hb = (uint32_t)__cvta_generic_to_shared(hs);
        const uint32_t qoffH = (uint32_t)(q * 68 * 4);

        if (tid < HH) hs[(tid >> 6) * 68 + (tid & 63)] = 0.0f;
        float hprev = 0.0f;
        BAR_SYNC(1, 256);

        for (int ch = 0; ch < NCH; ch++) {
            const int p = ch & 1;
            BAR_SYNC(2 + p, 512);             // xw[p] ready
            const float* xwb = xw_s + (size_t)p * CH * HH + c;
#pragma unroll
            for (int d = 0; d < CH; d++) {
                const int t = ch * CH + d;
                const float xwv = xwb[d * HH];
                const uint32_t ra = hb + ((t & 1) ? (uint32_t)(2 * 68 * 4) : 0u) + qoffH;
                ull a0 = packf2(0.f, 0.f), a1 = a0, a2 = a0, a3 = a0;
#pragma unroll
                for (int i = 0; i < 8; i++) {
                    ull p0, p1, p2, p3;
                    lds_v2u64(p0, p1, ra + (uint32_t)(i * 32));
                    lds_v2u64(p2, p3, ra + (uint32_t)(i * 32 + 16));
                    a0 = ffma2(p0, ureg[4 * i],     a0);
                    a1 = ffma2(p1, ureg[4 * i + 1], a1);
                    a2 = ffma2(p2, ureg[4 * i + 2], a2);
                    a3 = ffma2(p3, ureg[4 * i + 3], a3);
                }
                float2 f0 = unpackf2(a0), f1 = unpackf2(a1);
                float2 f2 = unpackf2(a2), f3 = unpackf2(a3);
                float part = ((f0.x + f0.y) + (f1.x + f1.y))
                           + ((f2.x + f2.y) + (f3.x + f3.y));
                float pre = part + __shfl_xor_sync(0xffffffffu, part, 16) + xwv;

                float z  = sigmoidf_(pre + bgj);
                float hh = tanhf_(pre + buj);
                float hn = z * hprev + (sz * (1.0f - z) + sn) * hh;
                float hc = gc * hn + c1;

                if (lane < 16) {
                    hs[((t & 1) ^ 1) * (2 * 68) + (c >> 6) * 68 + (c & 63)] = hc;
                    outp[(size_t)t * HH + c] = hc;
                }
                hprev = hc;
                BAR_SYNC(1, 256);
            }
            if (PROD) {
                __threadfence();
                BAR_SYNC(1, 256);
                if (tid == 0) st_release(flagp, (unsigned)((ch + 1) * CH));
            }
            BAR_ARRIVE(4 + p, 512);           // xw[p] free
        }
        if (lane < 16) hl[c] = hprev;
    } else {
        // ================= PROJ =================
        const int t2  = tid - 256;
        const int wp2 = t2 >> 5;
        const int qp  = lane >> 4;
        const int cp  = wp2 * 16 + (lane & 15);

        ull wreg[KH / 2];
#pragma unroll
        for (int m = 0; m < KH / 2; m++) {
            int k0 = KH * qp + 2 * m;
            wreg[m] = packf2(w[(size_t)k0 * HH + cp], w[(size_t)(k0 + 1) * HH + cp]);
        }

        const int rowd  = t2 / CPR;           // 0..CH-1 (valid for t2<NV4)
        const int e     = (t2 % CPR) * 4;
        const int ehalf = e / KH, ewit = e % KH;
        const uint32_t xb = (uint32_t)__cvta_generic_to_shared(xt);

        for (int ch = 0; ch < NCH; ch++) {
            const int p = ch & 1;
            if (!PROD) {
                while (ld_acquire(flagp) < (unsigned)((ch + 1) * CH)) { }
            }
            float4 sreg = make_float4(0.f, 0.f, 0.f, 0.f);
            if (t2 < NV4)
                sreg = __ldcg(reinterpret_cast<const float4*>(
                    xsrc + (size_t)(ch * CH + rowd) * KF + e));
            if (ch >= 2) BAR_SYNC(4 + p, 512);   // xw[p] free again
            if (t2 < NV4)
                *reinterpret_cast<float4*>(
                    &xt[p * XTS + rowd * (2 * KP) + ehalf * KP + ewit]) = sreg;
            BAR_SYNC(7, 256);                    // staging done (proj-internal)

            const uint32_t tb = xb + (uint32_t)(p * XTS * 4) + (uint32_t)(qp * KP * 4);
#pragma unroll
            for (int d = 0; d < CH; d++) {
                ull b0 = packf2(0.f, 0.f), b1 = b0;
                const uint32_t base = tb + (uint32_t)(d * (2 * KP) * 4);
#pragma unroll
                for (int i = 0; i < KH / 4; i++) {
                    ull p0, p1;
                    lds_v2u64(p0, p1, base + (uint32_t)(i * 16));
                    b0 = ffma2(p0, wreg[2 * i], b0);
                    b1 = ffma2(p1, wreg[2 * i + 1], b1);
                }
                float2 f0 = unpackf2(b0), f1 = unpackf2(b1);
                float pp = (f0.x + f0.y) + (f1.x + f1.y);
                pp += __shfl_xor_sync(0xffffffffu, pp, 16);
                if (lane < 16) xw_s[(size_t)(p * CH + d) * HH + cp] = pp;
            }
            BAR_ARRIVE(2 + p, 512);              // xw[p] ready
        }
    }
}

// ---------------- fused persistent kernel: 64 producer + 64 consumer CTAs
__global__ void __launch_bounds__(512, 1) fused_grnn(
    const float* __restrict__ x,
    const float* __restrict__ u0, const float* __restrict__ w0,
    const float* __restrict__ bg0, const float* __restrict__ bu0,
    const float* __restrict__ zeta0, const float* __restrict__ nu0,
    const float* __restrict__ lambd0, const float* __restrict__ gamma0,
    const float* __restrict__ u1, const float* __restrict__ w1,
    const float* __restrict__ bg1, const float* __restrict__ bu1,
    const float* __restrict__ zeta1, const float* __restrict__ nu1,
    const float* __restrict__ lambd1, const float* __restrict__ gamma1,
    float* __restrict__ out1, float* __restrict__ hn)
{
    __shared__ __align__(16) float hs[2 * 2 * 68];
    __shared__ __align__(16) float xt[2 * CH * 2 * 68];
    __shared__ __align__(16) float xw_s[2 * CH * HH];

    const int rank = blockIdx.x;
    if (rank < BB) {
        const int b = rank;
        role<II, true>(hs, xt, xw_s,
            x + (size_t)b * SS * II, u0, w0,
            bg0, bu0, zeta0, nu0, lambd0, gamma0,
            (float*)g_seq0 + (size_t)b * SS * HH,
            hn + (size_t)b * HH,
            &g_flag[b]);
    } else {
        const int b = rank - BB;
        role<HH, false>(hs, xt, xw_s,
            (const float*)g_seq0 + (size_t)b * SS * HH, u1, w1,
            bg1, bu1, zeta1, nu1, lambd1, gamma1,
            out1 + (size_t)b * SS * HH,
            hn + (size_t)(BB + b) * HH,
            &g_flag[b]);
    }
}

// ---------------- launch ----------------
extern "C" void kernel_launch(void* const* d_in, const int* in_sizes, int n_in,
                              void* d_out, int out_size)
{
    const float* x      = (const float*)d_in[0];
    const float* w0     = (const float*)d_in[1];
    const float* u0     = (const float*)d_in[2];
    const float* bg0    = (const float*)d_in[3];
    const float* bu0    = (const float*)d_in[4];
    const float* zeta0  = (const float*)d_in[5];
    const float* nu0    = (const float*)d_in[6];
    const float* lambd0 = (const float*)d_in[7];
    const float* gamma0 = (const float*)d_in[8];
    const float* w1     = (const float*)d_in[9];
    const float* u1     = (const float*)d_in[10];
    const float* bg1    = (const float*)d_in[11];
    const float* bu1    = (const float*)d_in[12];
    const float* zeta1  = (const float*)d_in[13];
    const float* nu1    = (const float*)d_in[14];
    const float* lambd1 = (const float*)d_in[15];
    const float* gamma1 = (const float*)d_in[16];

    float* out1 = (float*)d_out;                          // [B,S,H]
    float* hn   = out1 + (size_t)BB * SS * HH;            // [2,B,H]

    zero_flags<<<1, 64>>>();
    fused_grnn<<<2 * BB, 512>>>(x,
        u0, w0, bg0, bu0, zeta0, nu0, lambd0, gamma0,
        u1, w1, bg1, bu1, zeta1, nu1, lambd1, gamma1,
        out1, hn);
}